// round 17
// baseline (speedup 1.0000x reference)
#include <cuda_runtime.h>
#include <cuda_bf16.h>
#include <cuda_fp16.h>
#include <stdint.h>
#include <math.h>

#define BB 2
#define SS 2048
#define EE 1024
#define HH 16
#define DD 64
#define MM (BB*SS)
#define LOG2E 1.4426950408889634f

// Scratch (static device globals; no runtime allocation)
__device__ float g_vmean[BB*HH*DD];
__device__ float g_active[HH];
// Q pre-scaled by log2e, bf16 hi/lo, [B,H,S,D]
__device__ __align__(16) __nv_bfloat16 g_qh[BB*HH*SS*DD], g_ql[BB*HH*SS*DD];
// V stored fp16 TRANSPOSED d-major: word [bh][d][s2] = (V[2*s2][d], V[2*s2+1][d])
__device__ __align__(16) __half g_vpt[BB*HH*SS*DD];
// bf16 hi/lo K for attention QK
__device__ __align__(16) __nv_bfloat16 g_kh[BB*HH*SS*DD], g_kl[BB*HH*SS*DD];
// bf16 hi/lo operand arrays for bf16 mma GEMMs
__device__ __align__(16) __nv_bfloat16 g_xh[MM*EE],   g_xl[MM*EE];     // x
__device__ __align__(16) __nv_bfloat16 g_wh[3*EE*EE], g_wl[3*EE*EE];   // qkv_w
__device__ __align__(16) __nv_bfloat16 g_owh[EE*EE],  g_owl[EE*EE];    // out_w
__device__ __align__(16) __nv_bfloat16 g_aoh[MM*EE],  g_aol[MM*EE];    // attn out [B,S,H*D]

// ---------------------------------------------------------------------------
// helpers
// ---------------------------------------------------------------------------
__device__ __forceinline__ float uaf(unsigned u) { return __uint_as_float(u); }

__device__ __forceinline__ void mma_bf16(float c[4], const unsigned a[4], const unsigned b[2]) {
    asm volatile(
        "mma.sync.aligned.m16n8k16.row.col.f32.bf16.bf16.f32 "
        "{%0,%1,%2,%3}, {%4,%5,%6,%7}, {%8,%9}, {%0,%1,%2,%3};"
        : "+f"(c[0]), "+f"(c[1]), "+f"(c[2]), "+f"(c[3])
        : "r"(a[0]), "r"(a[1]), "r"(a[2]), "r"(a[3]),
          "r"(b[0]), "r"(b[1]));
}

__device__ __forceinline__ void mma_f16(float c[4], const unsigned a[4], const unsigned b[2]) {
    asm volatile(
        "mma.sync.aligned.m16n8k16.row.col.f32.f16.f16.f32 "
        "{%0,%1,%2,%3}, {%4,%5,%6,%7}, {%8,%9}, {%0,%1,%2,%3};"
        : "+f"(c[0]), "+f"(c[1]), "+f"(c[2]), "+f"(c[3])
        : "r"(a[0]), "r"(a[1]), "r"(a[2]), "r"(a[3]),
          "r"(b[0]), "r"(b[1]));
}

__device__ __forceinline__ void ldsm4(unsigned &r0, unsigned &r1, unsigned &r2,
                                      unsigned &r3, unsigned addr) {
    asm volatile("ldmatrix.sync.aligned.m8n8.x4.shared.b16 {%0,%1,%2,%3}, [%4];"
                 : "=r"(r0), "=r"(r1), "=r"(r2), "=r"(r3) : "r"(addr));
}

__device__ __forceinline__ void cp16(unsigned dst, const void* src) {
    asm volatile("cp.async.cg.shared.global [%0], [%1], 16;\n" :: "r"(dst), "l"(src));
}
__device__ __forceinline__ void cp_commit() {
    asm volatile("cp.async.commit_group;\n");
}
__device__ __forceinline__ void cp_wait1() {
    asm volatile("cp.async.wait_group 1;\n");
}
__device__ __forceinline__ void cp_wait0() {
    asm volatile("cp.async.wait_group 0;\n");
}

__device__ __forceinline__ unsigned bf2u(__nv_bfloat162 v) {
    return *(unsigned*)&v;
}
__device__ __forceinline__ unsigned h2u(__half2 v) {
    return *(unsigned*)&v;
}

__device__ __forceinline__ void split_one4(const float* __restrict__ src,
                                           __nv_bfloat16* __restrict__ h,
                                           __nv_bfloat16* __restrict__ l,
                                           size_t i) {
    float4 v = ((const float4*)src)[i];
    __nv_bfloat162 h01 = __floats2bfloat162_rn(v.x, v.y);
    __nv_bfloat162 h23 = __floats2bfloat162_rn(v.z, v.w);
    *(__nv_bfloat162*)(h + 4 * i)     = h01;
    *(__nv_bfloat162*)(h + 4 * i + 2) = h23;
    __nv_bfloat162 l01 = __floats2bfloat162_rn(
        v.x - __bfloat162float(h01.x), v.y - __bfloat162float(h01.y));
    __nv_bfloat162 l23 = __floats2bfloat162_rn(
        v.z - __bfloat162float(h23.x), v.w - __bfloat162float(h23.y));
    *(__nv_bfloat162*)(l + 4 * i)     = l01;
    *(__nv_bfloat162*)(l + 4 * i + 2) = l23;
}

// ---------------------------------------------------------------------------
// prep: head mask (block 0) + all three bf16 hi/lo splits in ONE launch
// ---------------------------------------------------------------------------
#define NX4 (MM*EE/4)
#define NW4 (3*EE*EE/4)
#define NO4 (EE*EE/4)
#define PREP_BLOCKS ((NX4 + NW4 + NO4) / 256)   // 8192

__global__ void prep_kernel(const float* __restrict__ x,
                            const float* __restrict__ w,
                            const float* __restrict__ ow,
                            const float* __restrict__ gates,
                            const float* __restrict__ imp,
                            const float* __restrict__ thr) {
    if (blockIdx.x == 0 && threadIdx.x < HH) {
        const int h = threadIdx.x;
        const float z  = gates[h] * imp[h];
        const float gs = 1.0f / (1.0f + expf(-z));
        g_active[h] = (gs > thr[0]) ? 1.0f : 0.0f;
    }
    const int i = blockIdx.x * 256 + threadIdx.x;
    if (i < NX4) {
        split_one4(x, g_xh, g_xl, i);
    } else if (i < NX4 + NW4) {
        split_one4(w, g_wh, g_wl, i - NX4);
    } else {
        split_one4(ow, g_owh, g_owl, i - NX4 - NW4);
    }
}

// ---------------------------------------------------------------------------
// vmean: grid (BB*HH, 8); warp w owns d-row; coalesced scan of d-major VPt.
// ---------------------------------------------------------------------------
__global__ void vmean_kernel() {
    const int bh = blockIdx.x;
    if (g_active[bh & (HH - 1)] == 0.0f) return;
    const int d    = blockIdx.y * 8 + (threadIdx.x >> 5);
    const int lane = threadIdx.x & 31;
    const __half2* row = (const __half2*)g_vpt + ((size_t)bh * DD + d) * (SS / 2);
    float sum = 0.f;
    for (int s2 = lane; s2 < SS / 2; s2 += 32) {
        float2 f = __half22float2(row[s2]);
        sum += f.x + f.y;
    }
#pragma unroll
    for (int o = 16; o > 0; o >>= 1)
        sum += __shfl_xor_sync(0xffffffffu, sum, o);
    if (lane == 0)
        g_vmean[bh * DD + d] = sum * (1.0f / SS);
}

// ---------------------------------------------------------------------------
// 3-term bf16-split GEMM on mma.sync.m16n8k16, ldmatrix frags, cp.async staging.
// MODE 0: qkv scatter epilogue (q pre-scaled bf16 hi/lo; V transposed fp16).
// MODE 1: row-major write.
// ---------------------------------------------------------------------------
#define GSTR  20
#define GARR  (128 * GSTR)
#define GSTG  (4 * GARR)
#define SMEM_GEMM (2 * GSTG * 4)    // 81920 B

template <int MODE>
__global__ void __launch_bounds__(256, 2) gemm_bf16_kernel(
    const __nv_bfloat16* __restrict__ Ahg, const __nv_bfloat16* __restrict__ Alg,
    const __nv_bfloat16* __restrict__ Bhg, const __nv_bfloat16* __restrict__ Blg,
    const float* __restrict__ bias, float* __restrict__ Y) {
    extern __shared__ unsigned gsm[];

    const int m0 = blockIdx.y * 128;
    const int n0 = blockIdx.x * 128;

    if (MODE == 0) {
        const int hA = (n0 & 1023) >> 6;
        if (g_active[hA] == 0.0f && g_active[hA + 1] == 0.0f) return;
    }

    const int tid  = threadIdx.x;
    const int lane = tid & 31;
    const int warp = tid >> 5;
    const int wm = (warp >> 2) * 64;
    const int wn = (warp & 3) * 32;
    const int grp = lane >> 2;
    const int tig = lane & 3;

    const int grow = tid >> 1;
    const int gkw  = (tid & 1) * 8;
    const __nv_bfloat16* Aph = Ahg + (size_t)(m0 + grow) * EE + gkw * 2;
    const __nv_bfloat16* Apl = Alg + (size_t)(m0 + grow) * EE + gkw * 2;
    const __nv_bfloat16* Bph = Bhg + (size_t)(n0 + grow) * EE + gkw * 2;
    const __nv_bfloat16* Bpl = Blg + (size_t)(n0 + grow) * EE + gkw * 2;

    const unsigned gb = (unsigned)__cvta_generic_to_shared(gsm);
    const int seg = lane >> 3, lr8 = lane & 7;
    const int arow = wm + (seg & 1) * 8 + lr8;
    const int acol = (seg >> 1) * 4;
    const int brow = wn + (seg >> 1) * 8 + lr8;
    const int bcol = (seg & 1) * 4;

    float acc[4][4][4];
#pragma unroll
    for (int i = 0; i < 4; i++)
#pragma unroll
        for (int j = 0; j < 4; j++)
#pragma unroll
            for (int r = 0; r < 4; r++) acc[i][j][r] = 0.f;

    auto issue_tile = [&](int kt, int st) {
        const size_t o = (size_t)kt * 32;
        const unsigned base = gb + (st * GSTG + grow * GSTR + gkw) * 4;
        cp16(base,                     Aph + o);
        cp16(base + 16,                Aph + o + 8);
        cp16(base + GARR * 4,          Apl + o);
        cp16(base + GARR * 4 + 16,     Apl + o + 8);
        cp16(base + 2 * GARR * 4,      Bph + o);
        cp16(base + 2 * GARR * 4 + 16, Bph + o + 8);
        cp16(base + 3 * GARR * 4,      Bpl + o);
        cp16(base + 3 * GARR * 4 + 16, Bpl + o + 8);
    };

    issue_tile(0, 0);
    cp_commit();

    const int NT = EE / 32;
    for (int kt = 0; kt < NT; kt++) {
        cp_wait0();
        __syncthreads();

        if (kt + 1 < NT) issue_tile(kt + 1, (kt + 1) & 1);
        cp_commit();

        const unsigned stb = gb + ((kt & 1) * GSTG) * 4;

#pragma unroll
        for (int ks = 0; ks < 2; ks++) {
            const int kw = ks * 8;
            unsigned bh[4][2], bl[4][2];
#pragma unroll
            for (int np = 0; np < 2; np++) {
                const unsigned addr =
                    stb + (2 * GARR + (brow + np * 16) * GSTR + kw + bcol) * 4;
                ldsm4(bh[2*np][0], bh[2*np][1], bh[2*np+1][0], bh[2*np+1][1], addr);
                ldsm4(bl[2*np][0], bl[2*np][1], bl[2*np+1][0], bl[2*np+1][1],
                      addr + GARR * 4);
            }
#pragma unroll
            for (int mi = 0; mi < 4; mi++) {
                unsigned ah[4], al[4];
                const unsigned addr =
                    stb + ((arow + mi * 16) * GSTR + kw + acol) * 4;
                ldsm4(ah[0], ah[1], ah[2], ah[3], addr);
                ldsm4(al[0], al[1], al[2], al[3], addr + GARR * 4);
#pragma unroll
                for (int ni = 0; ni < 4; ni++) {
                    mma_bf16(acc[mi][ni], ah, bh[ni]);
                    mma_bf16(acc[mi][ni], al, bh[ni]);
                    mma_bf16(acc[mi][ni], ah, bl[ni]);
                }
            }
        }
    }

    // epilogue
#pragma unroll
    for (int mi = 0; mi < 4; mi++) {
        const int rbase = m0 + wm + mi * 16 + grp;
#pragma unroll
        for (int ni = 0; ni < 4; ni++) {
            const int j = n0 + wn + ni * 8 + 2 * tig;
            const float b0 = bias[j], b1 = bias[j + 1];
#pragma unroll
            for (int rh = 0; rh < 2; rh++) {
                const int m = rbase + rh * 8;
                const float v0 = acc[mi][ni][rh * 2 + 0] + b0;
                const float v1 = acc[mi][ni][rh * 2 + 1] + b1;
                if (MODE == 1) {
                    float2 o; o.x = v0; o.y = v1;
                    *(float2*)(Y + (size_t)m * EE + j) = o;
                } else {
                    const int cc  = j >> 10;
                    const int rem = j & 1023;
                    const int h = rem >> 6, d = rem & 63;
                    const int bI = m >> 11;
                    const int s  = m & (SS - 1);
                    const size_t off = (((size_t)(bI * HH + h)) * SS + s) * DD + d;
                    if (cc == 0) {
                        // q scaled by log2e, bf16 hi/lo
                        const float q0v = v0 * LOG2E, q1v = v1 * LOG2E;
                        __nv_bfloat162 qh2 = __floats2bfloat162_rn(q0v, q1v);
                        __nv_bfloat162 ql2 = __floats2bfloat162_rn(
                            q0v - __bfloat162float(qh2.x),
                            q1v - __bfloat162float(qh2.y));
                        *(__nv_bfloat162*)(g_qh + off) = qh2;
                        *(__nv_bfloat162*)(g_ql + off) = ql2;
                    } else if (cc == 1) {
                        __nv_bfloat162 kh = __floats2bfloat162_rn(v0, v1);
                        __nv_bfloat162 kl = __floats2bfloat162_rn(
                            v0 - __bfloat162float(kh.x), v1 - __bfloat162float(kh.y));
                        *(__nv_bfloat162*)(g_kh + off) = kh;
                        *(__nv_bfloat162*)(g_kl + off) = kl;
                    } else {
                        const float am = g_active[h];
                        __half* base = g_vpt
                            + (((size_t)(bI * HH + h) * DD + d) * (SS / 2)
                               + (s >> 1)) * 2 + (s & 1);
                        base[0]  = __float2half_rn(v0 * am);
                        base[SS] = __float2half_rn(v1 * am);   // d+1 row
                    }
                }
            }
        }
    }
}

// ---------------------------------------------------------------------------
// Tensor-core flash attention, v10:
//  - Q fragments loaded directly as pre-split bf16 hi/lo words (log2-scaled)
//  - QK bf16 3-term (ldmatrix), softmax in log2 domain
//  - exp via h2exp2 (ex2.approx.f16x2): half the MUFU ops, output = P fp16 frag
//  - PV fp16: A-frag = own packed P regs; B-frag via ldmatrix on transposed VPt
// ---------------------------------------------------------------------------
#define KSTRW  36
#define TKHW   (64 * KSTRW)
#define VPTSTR 36
#define TVPTW  (64 * VPTSTR)
#define BUFW   (2 * TKHW + TVPTW)       // 6912 words
#define NSTG   3
#define SMEM_ATTN ((NSTG * BUFW + 64) * 4)   // 83200 B

__global__ void __launch_bounds__(256, 2) attn_tc_kernel() {
    extern __shared__ float sh[];

    const int tid  = threadIdx.x;
    const int lane = tid & 31;
    const int warp = tid >> 5;
    const int g8   = lane >> 2;
    const int tig  = lane & 3;
    const int wr   = warp * 16;

    const int b = blockIdx.z, h = blockIdx.y;
    const int q0 = blockIdx.x * 128;
    const size_t bh = (size_t)(b * HH + h) * SS * DD;

    if (g_active[h] == 0.0f) {
        const uint4 z = {0u, 0u, 0u, 0u};
        for (int i = tid; i < 128 * 8; i += 256) {
            const int r = i >> 3, c = (i & 7) * 8;
            const size_t off = ((size_t)(b * SS + q0 + r) * HH + h) * DD + c;
            *(uint4*)(g_aoh + off) = z;
            *(uint4*)(g_aol + off) = z;
        }
        return;
    }

    const unsigned sbase = (unsigned)__cvta_generic_to_shared(sh);
    float* vsm = sh + NSTG * BUFW;

    if (tid < 64)
        vsm[tid] = g_vmean[(b * HH + h) * DD + tid];

    const int seg = lane >> 3, lr8 = lane & 7;
    const int krow = (seg >> 1) * 8 + lr8;
    const int kcol = (seg & 1) * 4;

    // Q fragments: direct word loads of pre-split, pre-scaled bf16 hi/lo
    unsigned qh[4][4], ql[4][4];
    {
        const unsigned* qhw = (const unsigned*)g_qh + (bh >> 1);
        const unsigned* qlw = (const unsigned*)g_ql + (bh >> 1);
        const size_t rw0 = (size_t)(q0 + wr + g8) * (DD / 2);
        const size_t rw1 = rw0 + 8 * (DD / 2);
#pragma unroll
        for (int ks = 0; ks < 4; ks++) {
            const int wc = ks * 8 + tig;
            qh[ks][0] = qhw[rw0 + wc];
            qh[ks][1] = qhw[rw1 + wc];
            qh[ks][2] = qhw[rw0 + wc + 4];
            qh[ks][3] = qhw[rw1 + wc + 4];
            ql[ks][0] = qlw[rw0 + wc];
            ql[ks][1] = qlw[rw1 + wc];
            ql[ks][2] = qlw[rw0 + wc + 4];
            ql[ks][3] = qlw[rw1 + wc + 4];
        }
    }

    float o[8][4];
#pragma unroll
    for (int i = 0; i < 8; i++)
#pragma unroll
        for (int j = 0; j < 4; j++) o[i][j] = 0.f;
    float m0 = -1e30f, m1 = -1e30f, l0 = 0.f, l1 = 0.f;

    const unsigned* vptw = (const unsigned*)g_vpt + (size_t)(b * HH + h) * DD * (SS / 2);

    auto issue_tile = [&](int kvt, int st) {
        const int row = tid >> 2;       // 0..63
        const int t4  = tid & 3;
        const __nv_bfloat16* khp = g_kh + bh + (size_t)(kvt * 64 + row) * DD + t4 * 16;
        const __nv_bfloat16* klp = g_kl + bh + (size_t)(kvt * 64 + row) * DD + t4 * 16;
        const unsigned khd = sbase + (st * BUFW + row * KSTRW + t4 * 8) * 4;
        const unsigned kld = khd + TKHW * 4;
        cp16(khd,      khp);
        cp16(khd + 16, khp + 8);
        cp16(kld,      klp);
        cp16(kld + 16, klp + 8);
        const int qw = t4 * 8;
        const unsigned* vg = vptw + (size_t)row * (SS / 2) + kvt * 32 + qw;
        const unsigned vd = sbase + (st * BUFW + 2 * TKHW + row * VPTSTR + qw) * 4;
        cp16(vd,      vg);
        cp16(vd + 16, vg + 4);
    };

    issue_tile(0, 0); cp_commit();
    issue_tile(1, 1); cp_commit();

    const int NTILE = SS / 64;
    int stage = 0;
    for (int t = 0; t < NTILE; t++) {
        cp_wait1();
        __syncthreads();

        if (t + 2 < NTILE) {
            int st2 = stage + 2; if (st2 >= NSTG) st2 -= NSTG;
            issue_tile(t + 2, st2);
        }
        cp_commit();

        const unsigned stb = sbase + (stage * BUFW) * 4;
        const unsigned vtb = stb + (2 * TKHW) * 4;

        // ---- QK: bf16 3-term, ldmatrix K fragments (log2 domain) ----
        float c[8][4];
#pragma unroll
        for (int i = 0; i < 8; i++)
#pragma unroll
            for (int j = 0; j < 4; j++) c[i][j] = 0.f;
#pragma unroll
        for (int ks = 0; ks < 4; ks++) {
            const int kw = ks * 8;
#pragma unroll
            for (int ntp = 0; ntp < 4; ntp++) {
                unsigned kh0[2], kh1[2], kl0[2], kl1[2];
                const unsigned addr =
                    stb + ((krow + ntp * 16) * KSTRW + kw + kcol) * 4;
                ldsm4(kh0[0], kh0[1], kh1[0], kh1[1], addr);
                ldsm4(kl0[0], kl0[1], kl1[0], kl1[1], addr + TKHW * 4);
                mma_bf16(c[2*ntp],     qh[ks], kh0);
                mma_bf16(c[2*ntp],     ql[ks], kh0);
                mma_bf16(c[2*ntp],     qh[ks], kl0);
                mma_bf16(c[2*ntp + 1], qh[ks], kh1);
                mma_bf16(c[2*ntp + 1], ql[ks], kh1);
                mma_bf16(c[2*ntp + 1], qh[ks], kl1);
            }
        }

        // ---- online softmax (log2 domain); exp via f16x2 MUFU ----
        float mx0 = c[0][0], mx1 = c[0][2];
#pragma unroll
        for (int nt = 0; nt < 8; nt++) {
            mx0 = fmaxf(mx0, fmaxf(c[nt][0], c[nt][1]));
            mx1 = fmaxf(mx1, fmaxf(c[nt][2], c[nt][3]));
        }
        mx0 = fmaxf(mx0, __shfl_xor_sync(0xffffffffu, mx0, 1));
        mx0 = fmaxf(mx0, __shfl_xor_sync(0xffffffffu, mx0, 2));
        mx1 = fmaxf(mx1, __shfl_xor_sync(0xffffffffu, mx1, 1));
        mx1 = fmaxf(mx1, __shfl_xor_sync(0xffffffffu, mx1, 2));
        const float mn0 = fmaxf(m0, mx0);
        const float mn1 = fmaxf(m1, mx1);
        const float sc0 = exp2f(m0 - mn0);
        const float sc1 = exp2f(m1 - mn1);
        m0 = mn0; m1 = mn1;
#pragma unroll
        for (int dt = 0; dt < 8; dt++) {
            o[dt][0] *= sc0; o[dt][1] *= sc0;
            o[dt][2] *= sc1; o[dt][3] *= sc1;
        }
        unsigned hp[8][2];
        float s0 = 0.f, s1 = 0.f;
#pragma unroll
        for (int nt = 0; nt < 8; nt++) {
            __half2 d0 = __floats2half2_rn(c[nt][0] - m0, c[nt][1] - m0);
            __half2 d1 = __floats2half2_rn(c[nt][2] - m1, c[nt][3] - m1);
            __half2 e0 = h2exp2(d0);
            __half2 e1 = h2exp2(d1);
            hp[nt][0] = h2u(e0);
            hp[nt][1] = h2u(e1);
            float2 f0 = __half22float2(e0);
            float2 f1 = __half22float2(e1);
            s0 += f0.x + f0.y;
            s1 += f1.x + f1.y;
        }
        s0 += __shfl_xor_sync(0xffffffffu, s0, 1);
        s0 += __shfl_xor_sync(0xffffffffu, s0, 2);
        s1 += __shfl_xor_sync(0xffffffffu, s1, 1);
        s1 += __shfl_xor_sync(0xffffffffu, s1, 2);
        l0 = l0 * sc0 + s0;
        l1 = l1 * sc1 + s1;

        // ---- PV: fp16 m16n8k16; B-frags via ldmatrix on transposed VPt ----
#pragma unroll
        for (int ks = 0; ks < 4; ks++) {
            unsigned aa[4] = {hp[2*ks][0], hp[2*ks][1],
                              hp[2*ks + 1][0], hp[2*ks + 1][1]};
#pragma unroll
            for (int dtp = 0; dtp < 2; dtp++) {
                const unsigned a0 = vtb + ((dtp * 32 + lane) * VPTSTR + 8 * ks) * 4;
                unsigned b00, b01, b02, b03, b10, b11, b12, b13;
                ldsm4(b00, b01, b02, b03, a0);
                ldsm4(b10, b11, b12, b13, a0 + 16);
                unsigned bb0[2] = {b00, b10};
                unsigned bb1[2] = {b01, b11};
                unsigned bb2[2] = {b02, b12};
                unsigned bb3[2] = {b03, b13};
                mma_f16(o[dtp * 4 + 0], aa, bb0);
                mma_f16(o[dtp * 4 + 1], aa, bb1);
                mma_f16(o[dtp * 4 + 2], aa, bb2);
                mma_f16(o[dtp * 4 + 3], aa, bb3);
            }
        }

        stage = (stage + 1 == NSTG) ? 0 : stage + 1;
    }

    // epilogue: normalize, add vmean (from smem), emit bf16 hi/lo
    const float inv0 = 1.0f / l0;
    const float inv1 = 1.0f / l1;
    const int r0 = q0 + wr + g8;
    const size_t ob0 = ((size_t)(b * SS + r0) * HH + h) * DD;
    const size_t ob1 = ((size_t)(b * SS + r0 + 8) * HH + h) * DD;
#pragma unroll
    for (int dt = 0; dt < 8; dt++) {
        const int col = dt * 8 + 2 * tig;
        const float v0 = vsm[col], v1 = vsm[col + 1];
        const float f00 = o[dt][0] * inv0 + v0, f01 = o[dt][1] * inv0 + v1;
        const float f10 = o[dt][2] * inv1 + v0, f11 = o[dt][3] * inv1 + v1;
        __nv_bfloat162 h0 = __floats2bfloat162_rn(f00, f01);
        __nv_bfloat162 h1 = __floats2bfloat162_rn(f10, f11);
        __nv_bfloat162 lo0 = __floats2bfloat162_rn(
            f00 - __bfloat162float(h0.x), f01 - __bfloat162float(h0.y));
        __nv_bfloat162 lo1 = __floats2bfloat162_rn(
            f10 - __bfloat162float(h1.x), f11 - __bfloat162float(h1.y));
        *(__nv_bfloat162*)(g_aoh + ob0 + col) = h0;
        *(__nv_bfloat162*)(g_aol + ob0 + col) = lo0;
        *(__nv_bfloat162*)(g_aoh + ob1 + col) = h1;
        *(__nv_bfloat162*)(g_aol + ob1 + col) = lo1;
    }
}

// ---------------------------------------------------------------------------
extern "C" void kernel_launch(void* const* d_in, const int* in_sizes, int n_in,
                              void* d_out, int out_size) {
    const float* x      = (const float*)d_in[0];
    const float* qkv_w  = (const float*)d_in[1];
    const float* qkv_b  = (const float*)d_in[2];
    const float* out_w  = (const float*)d_in[3];
    const float* out_b  = (const float*)d_in[4];
    const float* gates  = (const float*)d_in[5];
    const float* imp    = (const float*)d_in[6];
    const float* thr    = (const float*)d_in[7];
    float* out = (float*)d_out;

    static bool attr_set = false;
    if (!attr_set) {
        cudaFuncSetAttribute(attn_tc_kernel,
                             cudaFuncAttributeMaxDynamicSharedMemorySize, SMEM_ATTN);
        cudaFuncSetAttribute(gemm_bf16_kernel<0>,
                             cudaFuncAttributeMaxDynamicSharedMemorySize, SMEM_GEMM);
        cudaFuncSetAttribute(gemm_bf16_kernel<1>,
                             cudaFuncAttributeMaxDynamicSharedMemorySize, SMEM_GEMM);
        attr_set = true;
    }

    __nv_bfloat16 *xh, *xl, *wh, *wl, *owh, *owl, *aoh, *aol;
    cudaGetSymbolAddress((void**)&xh,  g_xh);
    cudaGetSymbolAddress((void**)&xl,  g_xl);
    cudaGetSymbolAddress((void**)&wh,  g_wh);
    cudaGetSymbolAddress((void**)&wl,  g_wl);
    cudaGetSymbolAddress((void**)&owh, g_owh);
    cudaGetSymbolAddress((void**)&owl, g_owl);
    cudaGetSymbolAddress((void**)&aoh, g_aoh);
    cudaGetSymbolAddress((void**)&aol, g_aol);

    // fused mask + splits
    prep_kernel<<<PREP_BLOCKS, 256>>>(x, qkv_w, out_w, gates, imp, thr);

    // QKV projection
    {
        dim3 g(3 * EE / 128, MM / 128);      // 24 x 32
        gemm_bf16_kernel<0><<<g, 256, SMEM_GEMM>>>(xh, xl, wh, wl, qkv_b, nullptr);
    }

    // vmean
    {
        dim3 g(BB * HH, 8);
        vmean_kernel<<<g, 256>>>();
    }

    // Attention
    {
        dim3 g(SS / 128, HH, BB);            // 16 x 16 x 2
        attn_tc_kernel<<<g, 256, SMEM_ATTN>>>();
    }

    // Output projection
    {
        dim3 g(EE / 128, MM / 128);          // 8 x 32
        gemm_bf16_kernel<1><<<g, 256, SMEM_GEMM>>>(aoh, aol, owh, owl, out_b, out);
    }
}